// round 1
// baseline (speedup 1.0000x reference)
#include <cuda_runtime.h>
#include <cstdint>

#define DIMC 64
#define NBINS 4096
#define CHUNKS 12
#define ROWS_PER_CHUNK 32
#define IMG 384
#define WORDS 12          // 384 / 32
#define BATCH 32
#define OUTW 65

// Static device scratch (no allocations allowed)
__device__ float g_lut[NBINS * DIMC];              // 1 MB:  LUT2[pairPattern][channel], pre-scaled by 1/HW
__device__ int   g_part[BATCH * CHUNKS * NBINS];   // 6 MB:  per-block partial histograms (fully overwritten each call)

// ---------------------------------------------------------------------------
// Kernel 1: build the 12-bit pair LUT.
// pattern p: bits [4*ky + kx] = x[row i-1+ky][col j-1+kx] for pixel A at col j;
// pixel B (col j+1) reads the same nibbles shifted by one.
// LUT2[p][c] = (relu(bn(conv(A))) + relu(bn(conv(B)))) / (384*384)
// ---------------------------------------------------------------------------
__global__ __launch_bounds__(256) void lut_kernel(
    const float* __restrict__ w, const float* __restrict__ bias,
    const float* __restrict__ gamma, const float* __restrict__ beta,
    const float* __restrict__ mean, const float* __restrict__ var)
{
    int t = blockIdx.x * blockDim.x + threadIdx.x;   // 0 .. 4096*64-1
    int c = t & (DIMC - 1);
    int p = t >> 6;

    float A = gamma[c] * rsqrtf(var[c] + 1e-5f);
    float base = (bias[c] - mean[c]) * A + beta[c];

    float wk[9];
#pragma unroll
    for (int k = 0; k < 9; ++k) wk[k] = w[c * 9 + k];

    float da = 0.f, db = 0.f;
#pragma unroll
    for (int ky = 0; ky < 3; ++ky) {
#pragma unroll
        for (int kx = 0; kx < 3; ++kx) {
            int bp = 4 * ky + kx;
            if ((p >> bp) & 1)       da += wk[ky * 3 + kx];
            if ((p >> (bp + 1)) & 1) db += wk[ky * 3 + kx];
        }
    }
    float va = fmaxf(fmaf(A, da, base), 0.f);
    float vb = fmaxf(fmaf(A, db, base), 0.f);
    g_lut[p * DIMC + c] = (va + vb) * (1.0f / (384.0f * 384.0f));
}

// ---------------------------------------------------------------------------
// Kernel 2: LSB bit-plane + pair-pattern histogram.
// Grid (12 chunks, 32 images), 384 threads. Each block: 32 rows of one image.
// Phase A: warp w computes 32-pixel LSB bitboards for word-column w via ballot.
// Phase B: thread (row, word) handles 16 pixel-pairs with funnel shifts,
//          shared-memory atomics into a 4096-bin histogram.
// Phase C: plain STG flush to a private global buffer (no global atomics).
// ---------------------------------------------------------------------------
__global__ __launch_bounds__(384) void hist_kernel(const float* __restrict__ alpha)
{
    __shared__ uint32_t bits[ROWS_PER_CHUNK + 2][WORDS + 2];  // zero-padded cols
    __shared__ int hist[NBINS];

    int tid  = threadIdx.x;
    int b    = blockIdx.y;
    int r0   = blockIdx.x * ROWS_PER_CHUNK;
    int lane = tid & 31;
    int warp = tid >> 5;          // 0..11 = word column

    for (int i = tid; i < NBINS; i += 384) hist[i] = 0;
    if (tid < ROWS_PER_CHUNK + 2) { bits[tid][0] = 0u; bits[tid][WORDS + 1] = 0u; }

    const float* img = alpha + (size_t)b * IMG * IMG;
#pragma unroll 2
    for (int row = 0; row < ROWS_PER_CHUNK + 2; ++row) {
        int g = r0 - 1 + row;
        uint32_t wordbits = 0u;
        if (g >= 0 && g < IMG) {
            float v = img[g * IMG + warp * 32 + lane];
            int bit = ((int)(v * 255.0f)) & 1;
            wordbits = __ballot_sync(0xffffffffu, bit);
        }
        if (lane == 0) bits[row][warp + 1] = wordbits;
    }
    __syncthreads();

    int r  = tid / WORDS;   // 0..31 local row
    int wd = tid % WORDS;   // 0..11 word
    uint32_t p0 = bits[r][wd],     c0 = bits[r][wd + 1],     x0 = bits[r][wd + 2];
    uint32_t p1 = bits[r + 1][wd], c1 = bits[r + 1][wd + 1], x1 = bits[r + 1][wd + 2];
    uint32_t p2 = bits[r + 2][wd], c2 = bits[r + 2][wd + 1], x2 = bits[r + 2][wd + 2];

    {   // pair k=0: bits col-1..col+2 straddle previous word
        uint32_t n0 = __funnelshift_r(p0, c0, 31) & 0xF;
        uint32_t n1 = __funnelshift_r(p1, c1, 31) & 0xF;
        uint32_t n2 = __funnelshift_r(p2, c2, 31) & 0xF;
        atomicAdd(&hist[n0 | (n1 << 4) | (n2 << 8)], 1);
    }
#pragma unroll
    for (int k = 1; k < 16; ++k) {
        uint32_t n0 = __funnelshift_r(c0, x0, 2 * k - 1) & 0xF;
        uint32_t n1 = __funnelshift_r(c1, x1, 2 * k - 1) & 0xF;
        uint32_t n2 = __funnelshift_r(c2, x2, 2 * k - 1) & 0xF;
        atomicAdd(&hist[n0 | (n1 << 4) | (n2 << 8)], 1);
    }
    __syncthreads();

    int part = (b * CHUNKS + blockIdx.x) * NBINS;
    for (int i = tid; i < NBINS; i += 384) g_part[part + i] = hist[i];
}

// ---------------------------------------------------------------------------
// Kernel 3: per-image reduce of 12 partial histograms + hist@LUT contraction
// + marker check. One block per image, 256 threads.
// ---------------------------------------------------------------------------
__global__ __launch_bounds__(256) void reduce_kernel(
    const float* __restrict__ alpha, float* __restrict__ out)
{
    __shared__ float cnt[NBINS];
    __shared__ float red[4][DIMC];
    __shared__ float marker_sh;

    int tid = threadIdx.x;
    int b   = blockIdx.x;

    const int* part = g_part + b * CHUNKS * NBINS;
    for (int bin = tid; bin < NBINS; bin += 256) {
        int s = 0;
#pragma unroll
        for (int j = 0; j < CHUNKS; ++j) s += part[j * NBINS + bin];
        cnt[bin] = (float)s;
    }

    if (tid == 0) {
        // marker: first 32 flattened alpha values, MSB-first bytes vs 'AI24'
        uint32_t word = 0u;
        for (int j = 0; j < 32; ++j) {
            int bit = ((int)(alpha[j] * 255.0f)) & 1;
            word |= (uint32_t)bit << j;
        }
        // byte-reversal identity: brev(word) packs bytes as [b0 b1 b2 b3] MSB-first
        marker_sh = (__brev(word) == 0x41493234u) ? 1.0f : 0.0f;  // 'A','I','2','4'
    }
    __syncthreads();

    int c = tid & 63;
    int g = tid >> 6;       // 4 bin-groups
    float acc = 0.f;
#pragma unroll 4
    for (int bin = g; bin < NBINS; bin += 4)
        acc = fmaf(cnt[bin], g_lut[bin * DIMC + c], acc);
    red[g][c] = acc;
    __syncthreads();

    if (tid < DIMC)
        out[b * OUTW + tid] = red[0][tid] + red[1][tid] + red[2][tid] + red[3][tid];
    if (tid == 64)
        out[b * OUTW + 64] = marker_sh;
}

// ---------------------------------------------------------------------------
extern "C" void kernel_launch(void* const* d_in, const int* in_sizes, int n_in,
                              void* d_out, int out_size)
{
    const float* alpha  = (const float*)d_in[0];
    const float* conv_w = (const float*)d_in[1];
    const float* conv_b = (const float*)d_in[2];
    const float* bn_g   = (const float*)d_in[3];
    const float* bn_b   = (const float*)d_in[4];
    const float* bn_m   = (const float*)d_in[5];
    const float* bn_v   = (const float*)d_in[6];
    float* out = (float*)d_out;

    lut_kernel<<<(NBINS * DIMC) / 256, 256>>>(conv_w, conv_b, bn_g, bn_b, bn_m, bn_v);
    hist_kernel<<<dim3(CHUNKS, BATCH), 384>>>(alpha);
    reduce_kernel<<<BATCH, 256>>>(alpha, out);
}

// round 2
// speedup vs baseline: 3.1172x; 3.1172x over previous
#include <cuda_runtime.h>
#include <cstdint>

#define DIMC 64
#define NBINS 4096
#define CHUNKS 12
#define ROWS_PER_CHUNK 32
#define IMG 384
#define WORDS 12          // 384 / 32
#define BATCH 32
#define OUTW 65
#define BIN_GROUPS 8      // reduce-kernel bin parallelism
#define BINS_PER_GROUP (NBINS / BIN_GROUPS)   // 512

// Static device scratch (no allocations allowed)
__device__ float g_lut[NBINS * DIMC];              // 1 MB:  LUT2[pairPattern][channel], pre-scaled by 1/HW
__device__ int   g_part[BATCH * CHUNKS * NBINS];   // 6 MB:  per-block partial histograms

// ---------------------------------------------------------------------------
// Kernel 1: build the 12-bit pair LUT (4 patterns per thread) + zero d_out.
// pattern p: bits [4*ky + kx] = x[row i-1+ky][col j-1+kx] for pixel A;
// pixel B (next col) reads the same taps shifted one bit up.
// ---------------------------------------------------------------------------
__global__ __launch_bounds__(256) void lut_kernel(
    const float* __restrict__ w, const float* __restrict__ bias,
    const float* __restrict__ gamma, const float* __restrict__ beta,
    const float* __restrict__ mean, const float* __restrict__ var,
    float* __restrict__ out)
{
    int t = blockIdx.x * blockDim.x + threadIdx.x;   // 0 .. 65535
    int c = t & (DIMC - 1);
    int pb = (t >> 6) << 2;                          // 4 consecutive patterns

    if (t < BATCH * OUTW) out[t] = 0.0f;             // zero-init output (atomics later)

    float A = gamma[c] * rsqrtf(var[c] + 1e-5f);
    float base = (bias[c] - mean[c]) * A + beta[c];

    float wk[9];
#pragma unroll
    for (int k = 0; k < 9; ++k) wk[k] = w[c * 9 + k];

#pragma unroll
    for (int q = 0; q < 4; ++q) {
        int p = pb + q;
        float da = 0.f, db = 0.f;
#pragma unroll
        for (int ky = 0; ky < 3; ++ky) {
#pragma unroll
            for (int kx = 0; kx < 3; ++kx) {
                int bp = 4 * ky + kx;
                if ((p >> bp) & 1)       da += wk[ky * 3 + kx];
                if ((p >> (bp + 1)) & 1) db += wk[ky * 3 + kx];
            }
        }
        float va = fmaxf(fmaf(A, da, base), 0.f);
        float vb = fmaxf(fmaf(A, db, base), 0.f);
        g_lut[p * DIMC + c] = (va + vb) * (1.0f / (384.0f * 384.0f));
    }
}

// ---------------------------------------------------------------------------
// Kernel 2: LSB bit-plane + pair-pattern histogram.
// Grid (12 chunks, 32 images), 384 threads.
// Phase A: batch ALL 34 row loads into registers first (MLP=34), then ballots.
// Phase B: thread (row, word) handles 16 pixel-pairs, shared atomics.
// Phase C: plain STG flush to private global partials (no global atomics).
// ---------------------------------------------------------------------------
__global__ __launch_bounds__(384) void hist_kernel(const float* __restrict__ alpha)
{
    __shared__ uint32_t bits[ROWS_PER_CHUNK + 2][WORDS + 2];  // zero-padded cols
    __shared__ int hist[NBINS];

    int tid  = threadIdx.x;
    int b    = blockIdx.y;
    int r0   = blockIdx.x * ROWS_PER_CHUNK;
    int lane = tid & 31;
    int warp = tid >> 5;          // 0..11 = word column

    for (int i = tid; i < NBINS; i += 384) hist[i] = 0;
    if (tid < ROWS_PER_CHUNK + 2) { bits[tid][0] = 0u; bits[tid][WORDS + 1] = 0u; }

    const float* img = alpha + (size_t)b * IMG * IMG;

    // Phase A: issue all loads back-to-back, then convert+ballot.
    float v[ROWS_PER_CHUNK + 2];
#pragma unroll
    for (int row = 0; row < ROWS_PER_CHUNK + 2; ++row) {
        int g = r0 - 1 + row;
        v[row] = (g >= 0 && g < IMG) ? img[g * IMG + warp * 32 + lane] : 0.0f;
    }
#pragma unroll
    for (int row = 0; row < ROWS_PER_CHUNK + 2; ++row) {
        uint32_t wb = __ballot_sync(0xffffffffu, ((int)(v[row] * 255.0f)) & 1);
        if (lane == 0) bits[row][warp + 1] = wb;
    }
    __syncthreads();

    int r  = tid / WORDS;   // 0..31 local row
    int wd = tid % WORDS;   // 0..11 word
    uint32_t p0 = bits[r][wd],     c0 = bits[r][wd + 1],     x0 = bits[r][wd + 2];
    uint32_t p1 = bits[r + 1][wd], c1 = bits[r + 1][wd + 1], x1 = bits[r + 1][wd + 2];
    uint32_t p2 = bits[r + 2][wd], c2 = bits[r + 2][wd + 1], x2 = bits[r + 2][wd + 2];

    {   // pair k=0: window straddles previous word
        uint32_t n0 = __funnelshift_r(p0, c0, 31) & 0xF;
        uint32_t n1 = __funnelshift_r(p1, c1, 31) & 0xF;
        uint32_t n2 = __funnelshift_r(p2, c2, 31) & 0xF;
        atomicAdd(&hist[n0 | (n1 << 4) | (n2 << 8)], 1);
    }
#pragma unroll
    for (int k = 1; k < 16; ++k) {
        uint32_t n0 = __funnelshift_r(c0, x0, 2 * k - 1) & 0xF;
        uint32_t n1 = __funnelshift_r(c1, x1, 2 * k - 1) & 0xF;
        uint32_t n2 = __funnelshift_r(c2, x2, 2 * k - 1) & 0xF;
        atomicAdd(&hist[n0 | (n1 << 4) | (n2 << 8)], 1);
    }
    __syncthreads();

    int part = (b * CHUNKS + blockIdx.x) * NBINS;
    for (int i = tid; i < NBINS; i += 384) g_part[part + i] = hist[i];
}

// ---------------------------------------------------------------------------
// Kernel 3: grid (8 bin-groups, 32 images). Each block sums 12 partials for
// its 512 bins, contracts against the LUT slab (coalesced streaming reads),
// and atomically accumulates 64 channel partials into out.
// ---------------------------------------------------------------------------
__global__ __launch_bounds__(256) void reduce_kernel(
    const float* __restrict__ alpha, float* __restrict__ out)
{
    __shared__ float cnt[BINS_PER_GROUP];
    __shared__ float red[4][DIMC];

    int tid = threadIdx.x;
    int cg  = blockIdx.x;   // bin group
    int b   = blockIdx.y;   // image

    const int* part = g_part + b * CHUNKS * NBINS + cg * BINS_PER_GROUP;
    for (int bin = tid; bin < BINS_PER_GROUP; bin += 256) {
        int s = 0;
#pragma unroll
        for (int j = 0; j < CHUNKS; ++j) s += part[j * NBINS + bin];
        cnt[bin] = (float)s;
    }
    __syncthreads();

    int c = tid & 63;
    int g = tid >> 6;       // 4 bin sub-groups
    const float* lut = g_lut + (size_t)cg * BINS_PER_GROUP * DIMC;
    float acc = 0.f;
#pragma unroll 4
    for (int k = 0; k < BINS_PER_GROUP / 4; ++k) {
        int bin = k * 4 + g;
        acc = fmaf(cnt[bin], lut[bin * DIMC + c], acc);
    }
    red[g][c] = acc;
    __syncthreads();

    if (tid < DIMC)
        atomicAdd(&out[b * OUTW + tid],
                  red[0][tid] + red[1][tid] + red[2][tid] + red[3][tid]);

    // marker check: once per image
    if (cg == 0 && tid == 0) {
        uint32_t word = 0u;
#pragma unroll
        for (int j = 0; j < 32; ++j) {
            int bit = ((int)(alpha[j] * 255.0f)) & 1;
            word |= (uint32_t)bit << j;
        }
        out[b * OUTW + DIMC] = (__brev(word) == 0x41493234u) ? 1.0f : 0.0f;  // 'AI24'
    }
}

// ---------------------------------------------------------------------------
extern "C" void kernel_launch(void* const* d_in, const int* in_sizes, int n_in,
                              void* d_out, int out_size)
{
    const float* alpha  = (const float*)d_in[0];
    const float* conv_w = (const float*)d_in[1];
    const float* conv_b = (const float*)d_in[2];
    const float* bn_g   = (const float*)d_in[3];
    const float* bn_b   = (const float*)d_in[4];
    const float* bn_m   = (const float*)d_in[5];
    const float* bn_v   = (const float*)d_in[6];
    float* out = (float*)d_out;

    lut_kernel<<<(NBINS * DIMC / 4) / 256, 256>>>(conv_w, conv_b, bn_g, bn_b, bn_m, bn_v, out);
    hist_kernel<<<dim3(CHUNKS, BATCH), 384>>>(alpha);
    reduce_kernel<<<dim3(BIN_GROUPS, BATCH), 256>>>(alpha, out);
}

// round 3
// speedup vs baseline: 4.6345x; 1.4867x over previous
#include <cuda_runtime.h>
#include <cstdint>

#define DIMC 64
#define NBINS 4096
#define CHUNKS 6            // 64 rows per hist block (two 32-row passes)
#define IMG 384
#define WORDS 12            // 384 / 32
#define BATCH 32
#define OUTW 65
#define HIST_BLOCKS (BATCH * CHUNKS)    // 192
#define LUT_BLOCKS 64
#define RB_BINS 256         // reduce: bins per group
#define RB_IMGS 4           // reduce: images per block

// Static device scratch (no allocations allowed)
__device__ float g_lut[NBINS * DIMC];               // 1 MB: LUT2[pairPattern][channel], pre-scaled by 1/HW
__device__ int   g_part[BATCH * CHUNKS * NBINS];    // 3 MB: per-block partial histograms

// ---------------------------------------------------------------------------
// Fused kernel: blocks [0,192) histogram 64-row chunks; blocks [192,256)
// build the 12-bit pair LUT and zero d_out. One launch, one wave.
// ---------------------------------------------------------------------------
__global__ __launch_bounds__(384) void fused_kernel(
    const float* __restrict__ alpha,
    const float* __restrict__ w, const float* __restrict__ bias,
    const float* __restrict__ gamma, const float* __restrict__ beta,
    const float* __restrict__ mean, const float* __restrict__ var,
    float* __restrict__ out)
{
    int tid = threadIdx.x;

    if (blockIdx.x >= HIST_BLOCKS) {
        // ---------------- LUT role ----------------
        int t = (blockIdx.x - HIST_BLOCKS) * 384 + tid;   // 0 .. 24575
        if (t < BATCH * OUTW) out[t] = 0.0f;              // zero-init output

        int c  = t & (DIMC - 1);
        int p0 = t >> 6;                                  // 0..383

        float A = gamma[c] * rsqrtf(var[c] + 1e-5f);
        float base = (bias[c] - mean[c]) * A + beta[c];
        float wk[9];
#pragma unroll
        for (int k = 0; k < 9; ++k) wk[k] = w[c * 9 + k];

        for (int p = p0; p < NBINS; p += 384) {
            float da = 0.f, db = 0.f;
#pragma unroll
            for (int ky = 0; ky < 3; ++ky)
#pragma unroll
                for (int kx = 0; kx < 3; ++kx) {
                    int bp = 4 * ky + kx;
                    if ((p >> bp) & 1)       da += wk[ky * 3 + kx];
                    if ((p >> (bp + 1)) & 1) db += wk[ky * 3 + kx];
                }
            float va = fmaxf(fmaf(A, da, base), 0.f);
            float vb = fmaxf(fmaf(A, db, base), 0.f);
            g_lut[p * DIMC + c] = (va + vb) * (1.0f / (384.0f * 384.0f));
        }
        return;
    }

    // ---------------- histogram role ----------------
    __shared__ uint32_t bits[34][WORDS + 2];   // 32+2 rows, zero-padded cols
    __shared__ int hist[NBINS];

    int b     = blockIdx.x / CHUNKS;
    int chunk = blockIdx.x % CHUNKS;
    int lane  = tid & 31;
    int warp  = tid >> 5;                      // 0..11 = word column

    for (int i = tid; i < NBINS; i += 384) hist[i] = 0;
    if (tid < 34) { bits[tid][0] = 0u; bits[tid][WORDS + 1] = 0u; }

    const float* img = alpha + (size_t)b * IMG * IMG;
    int r  = tid / WORDS;   // 0..31 local row  (384 = 32*12 exactly)
    int wd = tid % WORDS;

#pragma unroll
    for (int pass = 0; pass < 2; ++pass) {
        int base_row = chunk * 64 + pass * 32;

        // batch all 34 loads (MLP), then ballots
        float v[34];
#pragma unroll
        for (int row = 0; row < 34; ++row) {
            int g = base_row - 1 + row;
            v[row] = (g >= 0 && g < IMG) ? img[g * IMG + warp * 32 + lane] : 0.0f;
        }
#pragma unroll
        for (int row = 0; row < 34; ++row) {
            uint32_t wb = __ballot_sync(0xffffffffu, ((int)(v[row] * 255.0f)) & 1);
            if (lane == 0) bits[row][warp + 1] = wb;
        }
        __syncthreads();

        uint32_t p0 = bits[r][wd],     c0 = bits[r][wd + 1],     x0 = bits[r][wd + 2];
        uint32_t p1 = bits[r + 1][wd], c1 = bits[r + 1][wd + 1], x1 = bits[r + 1][wd + 2];
        uint32_t p2 = bits[r + 2][wd], c2 = bits[r + 2][wd + 1], x2 = bits[r + 2][wd + 2];

        {   // pair k=0: window straddles previous word
            uint32_t n0 = __funnelshift_r(p0, c0, 31) & 0xF;
            uint32_t n1 = __funnelshift_r(p1, c1, 31) & 0xF;
            uint32_t n2 = __funnelshift_r(p2, c2, 31) & 0xF;
            atomicAdd(&hist[n0 | (n1 << 4) | (n2 << 8)], 1);
        }
#pragma unroll
        for (int k = 1; k < 16; ++k) {
            uint32_t n0 = __funnelshift_r(c0, x0, 2 * k - 1) & 0xF;
            uint32_t n1 = __funnelshift_r(c1, x1, 2 * k - 1) & 0xF;
            uint32_t n2 = __funnelshift_r(c2, x2, 2 * k - 1) & 0xF;
            atomicAdd(&hist[n0 | (n1 << 4) | (n2 << 8)], 1);
        }
        __syncthreads();   // protect bits[] before next pass overwrites
    }

    int part = blockIdx.x * NBINS;
    for (int i = tid; i < NBINS; i += 384) g_part[part + i] = hist[i];
}

// ---------------------------------------------------------------------------
// Reduce: grid (16 bin-groups, 8 image-groups). Each block: 256 bins × 4
// images. One LUT load feeds 4 independent FMA chains (one per image).
// ---------------------------------------------------------------------------
__global__ __launch_bounds__(256) void reduce_kernel(
    const float* __restrict__ alpha, float* __restrict__ out)
{
    __shared__ float cnt[RB_IMGS][RB_BINS];
    __shared__ float red[4][RB_IMGS][DIMC];

    int tid = threadIdx.x;
    int cg  = blockIdx.x;                  // bin group: bins [cg*256, cg*256+256)
    int ig  = blockIdx.y;                  // images [ig*4, ig*4+4)

#pragma unroll
    for (int i = 0; i < RB_IMGS; ++i) {
        int b = ig * RB_IMGS + i;
        const int* part = g_part + b * CHUNKS * NBINS + cg * RB_BINS;
        int s = 0;
#pragma unroll
        for (int j = 0; j < CHUNKS; ++j) s += part[j * NBINS + tid];
        cnt[i][tid] = (float)s;
    }
    __syncthreads();

    int c = tid & 63;
    int g = tid >> 6;                      // 4 bin sub-groups
    const float* lut = g_lut + (size_t)cg * RB_BINS * DIMC;

    float acc0 = 0.f, acc1 = 0.f, acc2 = 0.f, acc3 = 0.f;
#pragma unroll 8
    for (int k = 0; k < RB_BINS / 4; ++k) {
        int bin = 4 * k + g;
        float l = lut[bin * DIMC + c];
        acc0 = fmaf(cnt[0][bin], l, acc0);
        acc1 = fmaf(cnt[1][bin], l, acc1);
        acc2 = fmaf(cnt[2][bin], l, acc2);
        acc3 = fmaf(cnt[3][bin], l, acc3);
    }
    red[g][0][c] = acc0; red[g][1][c] = acc1;
    red[g][2][c] = acc2; red[g][3][c] = acc3;
    __syncthreads();

    if (tid < DIMC) {
#pragma unroll
        for (int i = 0; i < RB_IMGS; ++i) {
            float s = red[0][i][tid] + red[1][i][tid] + red[2][i][tid] + red[3][i][tid];
            atomicAdd(&out[(ig * RB_IMGS + i) * OUTW + tid], s);
        }
    }

    // marker check: one thread total; broadcast to all 32 rows
    if (cg == 0 && blockIdx.y == 0 && tid == 0) {
        uint32_t word = 0u;
#pragma unroll
        for (int j = 0; j < 32; ++j) {
            int bit = ((int)(alpha[j] * 255.0f)) & 1;
            word |= (uint32_t)bit << j;
        }
        float m = (__brev(word) == 0x41493234u) ? 1.0f : 0.0f;   // 'AI24'
        for (int b = 0; b < BATCH; ++b) out[b * OUTW + DIMC] = m;
    }
}

// ---------------------------------------------------------------------------
extern "C" void kernel_launch(void* const* d_in, const int* in_sizes, int n_in,
                              void* d_out, int out_size)
{
    const float* alpha  = (const float*)d_in[0];
    const float* conv_w = (const float*)d_in[1];
    const float* conv_b = (const float*)d_in[2];
    const float* bn_g   = (const float*)d_in[3];
    const float* bn_b   = (const float*)d_in[4];
    const float* bn_m   = (const float*)d_in[5];
    const float* bn_v   = (const float*)d_in[6];
    float* out = (float*)d_out;

    fused_kernel<<<HIST_BLOCKS + LUT_BLOCKS, 384>>>(
        alpha, conv_w, conv_b, bn_g, bn_b, bn_m, bn_v, out);
    reduce_kernel<<<dim3(16, 8), 256>>>(alpha, out);
}

// round 4
// speedup vs baseline: 5.1843x; 1.1186x over previous
#include <cuda_runtime.h>
#include <cstdint>

#define DIMC 64
#define NBINS 4096
#define CHUNKS 6            // 64 rows per hist block (two 32-row passes)
#define IMG 384
#define WORDS 12            // 384 / 32
#define BATCH 32
#define OUTW 65
#define HIST_BLOCKS (BATCH * CHUNKS)    // 192
#define LUT_BLOCKS 64
#define RB_BINS 128         // reduce: bins per block
#define RB_IMGS 2           // reduce: images per block
#define BIN_GROUPS (NBINS / RB_BINS)    // 32
#define IMG_GROUPS (BATCH / RB_IMGS)    // 16

// Static device scratch (no allocations allowed)
__device__ float g_lut[NBINS * DIMC];               // 1 MB: LUT2[pairPattern][channel], pre-scaled by 1/HW
__device__ int   g_part[BATCH * CHUNKS * NBINS];    // 3 MB: per-block partial histograms

// ---------------------------------------------------------------------------
// Fused kernel: blocks [0,192) histogram 64-row chunks; blocks [192,256)
// build the 12-bit pair LUT and zero d_out. One launch, one wave.
// ---------------------------------------------------------------------------
__global__ __launch_bounds__(384) void fused_kernel(
    const float* __restrict__ alpha,
    const float* __restrict__ w, const float* __restrict__ bias,
    const float* __restrict__ gamma, const float* __restrict__ beta,
    const float* __restrict__ mean, const float* __restrict__ var,
    float* __restrict__ out)
{
    int tid = threadIdx.x;

    if (blockIdx.x >= HIST_BLOCKS) {
        // ---------------- LUT role ----------------
        int t = (blockIdx.x - HIST_BLOCKS) * 384 + tid;   // 0 .. 24575
        if (t < BATCH * OUTW) out[t] = 0.0f;              // zero-init output

        int c  = t & (DIMC - 1);
        int p0 = t >> 6;                                  // 0..383

        float A = gamma[c] * rsqrtf(var[c] + 1e-5f);
        float base = (bias[c] - mean[c]) * A + beta[c];
        float wk[9];
#pragma unroll
        for (int k = 0; k < 9; ++k) wk[k] = w[c * 9 + k];

        for (int p = p0; p < NBINS; p += 384) {
            float da = 0.f, db = 0.f;
#pragma unroll
            for (int ky = 0; ky < 3; ++ky)
#pragma unroll
                for (int kx = 0; kx < 3; ++kx) {
                    int bp = 4 * ky + kx;
                    if ((p >> bp) & 1)       da += wk[ky * 3 + kx];
                    if ((p >> (bp + 1)) & 1) db += wk[ky * 3 + kx];
                }
            float va = fmaxf(fmaf(A, da, base), 0.f);
            float vb = fmaxf(fmaf(A, db, base), 0.f);
            g_lut[p * DIMC + c] = (va + vb) * (1.0f / (384.0f * 384.0f));
        }
        return;
    }

    // ---------------- histogram role ----------------
    __shared__ uint32_t bits[34][WORDS + 2];   // 32+2 rows, zero-padded cols
    __shared__ int hist[NBINS];

    int b     = blockIdx.x / CHUNKS;
    int chunk = blockIdx.x % CHUNKS;
    int lane  = tid & 31;
    int warp  = tid >> 5;                      // 0..11 = word column

    for (int i = tid; i < NBINS; i += 384) hist[i] = 0;
    if (tid < 34) { bits[tid][0] = 0u; bits[tid][WORDS + 1] = 0u; }

    const float* img = alpha + (size_t)b * IMG * IMG;
    int r  = tid / WORDS;   // 0..31 local row  (384 = 32*12 exactly)
    int wd = tid % WORDS;

#pragma unroll
    for (int pass = 0; pass < 2; ++pass) {
        int base_row = chunk * 64 + pass * 32;

        // batch all 34 loads (MLP), then ballots
        float v[34];
#pragma unroll
        for (int row = 0; row < 34; ++row) {
            int g = base_row - 1 + row;
            v[row] = (g >= 0 && g < IMG) ? img[g * IMG + warp * 32 + lane] : 0.0f;
        }
#pragma unroll
        for (int row = 0; row < 34; ++row) {
            uint32_t wb = __ballot_sync(0xffffffffu, ((int)(v[row] * 255.0f)) & 1);
            if (lane == 0) bits[row][warp + 1] = wb;
        }
        __syncthreads();

        uint32_t p0 = bits[r][wd],     c0 = bits[r][wd + 1],     x0 = bits[r][wd + 2];
        uint32_t p1 = bits[r + 1][wd], c1 = bits[r + 1][wd + 1], x1 = bits[r + 1][wd + 2];
        uint32_t p2 = bits[r + 2][wd], c2 = bits[r + 2][wd + 1], x2 = bits[r + 2][wd + 2];

        {   // pair k=0: window straddles previous word
            uint32_t n0 = __funnelshift_r(p0, c0, 31) & 0xF;
            uint32_t n1 = __funnelshift_r(p1, c1, 31) & 0xF;
            uint32_t n2 = __funnelshift_r(p2, c2, 31) & 0xF;
            atomicAdd(&hist[n0 | (n1 << 4) | (n2 << 8)], 1);
        }
#pragma unroll
        for (int k = 1; k < 16; ++k) {
            uint32_t n0 = __funnelshift_r(c0, x0, 2 * k - 1) & 0xF;
            uint32_t n1 = __funnelshift_r(c1, x1, 2 * k - 1) & 0xF;
            uint32_t n2 = __funnelshift_r(c2, x2, 2 * k - 1) & 0xF;
            atomicAdd(&hist[n0 | (n1 << 4) | (n2 << 8)], 1);
        }
        __syncthreads();   // protect bits[] before next pass overwrites
    }

    // vectorized flush (no global atomics)
    int4* dst = (int4*)(g_part + blockIdx.x * NBINS);
    const int4* src = (const int4*)hist;
    for (int i = tid; i < NBINS / 4; i += 384) dst[i] = src[i];
}

// ---------------------------------------------------------------------------
// Reduce: grid (32 bin-groups, 16 image-pairs) = 512 blocks × 256 threads.
// ~27 warps/SM: latency hidden by warp parallelism, not ILP.
// Phase 1: 64 threads do int4 partial merges (MLP=6 vec loads each).
// Phase 2: all 256 threads contract 128 bins × 64ch × 2 images.
// ---------------------------------------------------------------------------
__global__ __launch_bounds__(256) void reduce_kernel(
    const float* __restrict__ alpha, float* __restrict__ out)
{
    __shared__ float cnt[RB_IMGS][RB_BINS];
    __shared__ float red[4][RB_IMGS][DIMC];

    int tid = threadIdx.x;
    int cg  = blockIdx.x;                  // bin group: bins [cg*128, cg*128+128)
    int ig  = blockIdx.y;                  // images {ig*2, ig*2+1}

    if (tid < 64) {
        int i = tid >> 5;                  // image within pair
        int q = tid & 31;                  // int4 quad (bins 4q..4q+3)
        int b = ig * RB_IMGS + i;
        const int4* part =
            (const int4*)(g_part + b * CHUNKS * NBINS + cg * RB_BINS) + q;
        int4 s = make_int4(0, 0, 0, 0);
#pragma unroll
        for (int j = 0; j < CHUNKS; ++j) {
            int4 p = part[j * (NBINS / 4)];
            s.x += p.x; s.y += p.y; s.z += p.z; s.w += p.w;
        }
        cnt[i][4 * q + 0] = (float)s.x;
        cnt[i][4 * q + 1] = (float)s.y;
        cnt[i][4 * q + 2] = (float)s.z;
        cnt[i][4 * q + 3] = (float)s.w;
    }
    __syncthreads();

    int c = tid & 63;
    int g = tid >> 6;                      // 4 bin sub-chains
    const float* lut = g_lut + (size_t)cg * RB_BINS * DIMC + c;

    float a0 = 0.f, a1 = 0.f;
#pragma unroll 8
    for (int k = 0; k < RB_BINS / 4; ++k) {
        int bin = 4 * k + g;
        float l = lut[bin * DIMC];         // coalesced 128B; cnt[] is broadcast
        a0 = fmaf(cnt[0][bin], l, a0);
        a1 = fmaf(cnt[1][bin], l, a1);
    }
    red[g][0][c] = a0;
    red[g][1][c] = a1;
    __syncthreads();

    if (tid < 128) {
        int i = tid >> 6;                  // image within pair
        int ch = tid & 63;
        float s = red[0][i][ch] + red[1][i][ch] + red[2][i][ch] + red[3][i][ch];
        atomicAdd(&out[(ig * RB_IMGS + i) * OUTW + ch], s);
    }

    // marker check: one thread total; broadcast to all 32 rows
    if (cg == 0 && blockIdx.y == 0 && tid == 0) {
        uint32_t word = 0u;
#pragma unroll
        for (int j = 0; j < 32; ++j) {
            int bit = ((int)(alpha[j] * 255.0f)) & 1;
            word |= (uint32_t)bit << j;
        }
        float m = (__brev(word) == 0x41493234u) ? 1.0f : 0.0f;   // 'AI24'
        for (int b = 0; b < BATCH; ++b) out[b * OUTW + DIMC] = m;
    }
}

// ---------------------------------------------------------------------------
extern "C" void kernel_launch(void* const* d_in, const int* in_sizes, int n_in,
                              void* d_out, int out_size)
{
    const float* alpha  = (const float*)d_in[0];
    const float* conv_w = (const float*)d_in[1];
    const float* conv_b = (const float*)d_in[2];
    const float* bn_g   = (const float*)d_in[3];
    const float* bn_b   = (const float*)d_in[4];
    const float* bn_m   = (const float*)d_in[5];
    const float* bn_v   = (const float*)d_in[6];
    float* out = (float*)d_out;

    fused_kernel<<<HIST_BLOCKS + LUT_BLOCKS, 384>>>(
        alpha, conv_w, conv_b, bn_g, bn_b, bn_m, bn_v, out);
    reduce_kernel<<<dim3(BIN_GROUPS, IMG_GROUPS), 256>>>(alpha, out);
}

// round 5
// speedup vs baseline: 5.2064x; 1.0043x over previous
#include <cuda_runtime.h>
#include <cstdint>

#define DIMC 64
#define NBINS 4096
#define CHUNKS 6            // 64 rows per hist block (two 32-row passes)
#define IMG 384
#define WORDS 12            // 384 / 32
#define BATCH 32
#define OUTW 65
#define HIST_BLOCKS (BATCH * CHUNKS)    // 192
#define LUT_BLOCKS 64
#define RB_BINS 128         // reduce: bins per block
#define RB_IMGS 4           // reduce: images per block
#define BIN_GROUPS (NBINS / RB_BINS)    // 32
#define IMG_GROUPS (BATCH / RB_IMGS)    // 8
#define KCH (RB_BINS / 4)   // 32 lut registers per thread

// Static device scratch (no allocations allowed)
__device__ float g_lut[NBINS * DIMC];               // 1 MB: LUT2[pairPattern][channel], pre-scaled by 1/HW
__device__ int   g_part[BATCH * CHUNKS * NBINS];    // 3 MB: per-block partial histograms

// ---------------------------------------------------------------------------
// Fused kernel: blocks [0,192) histogram 64-row chunks; blocks [192,256)
// build the 12-bit pair LUT and zero d_out. One launch, one wave.
// ---------------------------------------------------------------------------
__global__ __launch_bounds__(384) void fused_kernel(
    const float* __restrict__ alpha,
    const float* __restrict__ w, const float* __restrict__ bias,
    const float* __restrict__ gamma, const float* __restrict__ beta,
    const float* __restrict__ mean, const float* __restrict__ var,
    float* __restrict__ out)
{
    int tid = threadIdx.x;

    if (blockIdx.x >= HIST_BLOCKS) {
        // ---------------- LUT role ----------------
        int t = (blockIdx.x - HIST_BLOCKS) * 384 + tid;   // 0 .. 24575
        if (t < BATCH * OUTW) out[t] = 0.0f;              // zero-init output

        int c  = t & (DIMC - 1);
        int p0 = t >> 6;                                  // 0..383

        float A = gamma[c] * rsqrtf(var[c] + 1e-5f);
        float base = (bias[c] - mean[c]) * A + beta[c];
        float wk[9];
#pragma unroll
        for (int k = 0; k < 9; ++k) wk[k] = w[c * 9 + k];

        for (int p = p0; p < NBINS; p += 384) {
            float da = 0.f, db = 0.f;
#pragma unroll
            for (int ky = 0; ky < 3; ++ky)
#pragma unroll
                for (int kx = 0; kx < 3; ++kx) {
                    int bp = 4 * ky + kx;
                    if ((p >> bp) & 1)       da += wk[ky * 3 + kx];
                    if ((p >> (bp + 1)) & 1) db += wk[ky * 3 + kx];
                }
            float va = fmaxf(fmaf(A, da, base), 0.f);
            float vb = fmaxf(fmaf(A, db, base), 0.f);
            g_lut[p * DIMC + c] = (va + vb) * (1.0f / (384.0f * 384.0f));
        }
        return;
    }

    // ---------------- histogram role ----------------
    __shared__ uint32_t bits[34][WORDS + 2];   // 32+2 rows, zero-padded cols
    __shared__ int hist[NBINS];

    int b     = blockIdx.x / CHUNKS;
    int chunk = blockIdx.x % CHUNKS;
    int lane  = tid & 31;
    int warp  = tid >> 5;                      // 0..11 = word column

    for (int i = tid; i < NBINS; i += 384) hist[i] = 0;
    if (tid < 34) { bits[tid][0] = 0u; bits[tid][WORDS + 1] = 0u; }

    const float* img = alpha + (size_t)b * IMG * IMG;
    int r  = tid / WORDS;   // 0..31 local row  (384 = 32*12 exactly)
    int wd = tid % WORDS;

#pragma unroll
    for (int pass = 0; pass < 2; ++pass) {
        int base_row = chunk * 64 + pass * 32;

        // batch all 34 loads (MLP), then ballots
        float v[34];
#pragma unroll
        for (int row = 0; row < 34; ++row) {
            int g = base_row - 1 + row;
            v[row] = (g >= 0 && g < IMG) ? img[g * IMG + warp * 32 + lane] : 0.0f;
        }
#pragma unroll
        for (int row = 0; row < 34; ++row) {
            uint32_t wb = __ballot_sync(0xffffffffu, ((int)(v[row] * 255.0f)) & 1);
            if (lane == 0) bits[row][warp + 1] = wb;
        }
        __syncthreads();

        uint32_t p0 = bits[r][wd],     c0 = bits[r][wd + 1],     x0 = bits[r][wd + 2];
        uint32_t p1 = bits[r + 1][wd], c1 = bits[r + 1][wd + 1], x1 = bits[r + 1][wd + 2];
        uint32_t p2 = bits[r + 2][wd], c2 = bits[r + 2][wd + 1], x2 = bits[r + 2][wd + 2];

        {   // pair k=0: window straddles previous word
            uint32_t n0 = __funnelshift_r(p0, c0, 31) & 0xF;
            uint32_t n1 = __funnelshift_r(p1, c1, 31) & 0xF;
            uint32_t n2 = __funnelshift_r(p2, c2, 31) & 0xF;
            atomicAdd(&hist[n0 | (n1 << 4) | (n2 << 8)], 1);
        }
#pragma unroll
        for (int k = 1; k < 16; ++k) {
            uint32_t n0 = __funnelshift_r(c0, x0, 2 * k - 1) & 0xF;
            uint32_t n1 = __funnelshift_r(c1, x1, 2 * k - 1) & 0xF;
            uint32_t n2 = __funnelshift_r(c2, x2, 2 * k - 1) & 0xF;
            atomicAdd(&hist[n0 | (n1 << 4) | (n2 << 8)], 1);
        }
        __syncthreads();   // protect bits[] before next pass overwrites
    }

    // vectorized flush (no global atomics)
    int4* dst = (int4*)(g_part + blockIdx.x * NBINS);
    const int4* src = (const int4*)hist;
    for (int i = tid; i < NBINS / 4; i += 384) dst[i] = src[i];
}

// ---------------------------------------------------------------------------
// Reduce: grid (32 bin-groups, 8 image-quads) = 256 blocks × 256 threads,
// single wave. Thread (c, g) holds its 32 LUT values in registers (one
// batched coalesced load burst), then runs 4 independent image chains off
// broadcast LDS.128 reads of the image-major count vector.
// ---------------------------------------------------------------------------
__global__ __launch_bounds__(256) void reduce_kernel(
    const float* __restrict__ alpha, float* __restrict__ out)
{
    __shared__ float4 cnt4[RB_BINS];            // [bin] -> counts of 4 images
    __shared__ float  red[4][RB_IMGS][DIMC];

    int tid = threadIdx.x;
    int cg  = blockIdx.x;                       // bins [cg*128, cg*128+128)
    int ig  = blockIdx.y;                       // images [ig*4, ig*4+4)

    int c = tid & 63;
    int g = tid >> 6;                           // 0..3 bin sub-chain

    // LUT into registers: one fully-batched, coalesced burst (MLP=32)
    const float* lut = g_lut + (size_t)cg * RB_BINS * DIMC + c;
    float l[KCH];
#pragma unroll
    for (int k = 0; k < KCH; ++k) l[k] = lut[(4 * k + g) * DIMC];

    // Phase 1: merge 6 partials; 128 threads, int4-vectorized, image-major out
    if (tid < 128) {
        int i = tid >> 5;                       // image within quad
        int q = tid & 31;                       // bin quad
        int b = ig * RB_IMGS + i;
        const int4* part =
            (const int4*)(g_part + (b * CHUNKS) * NBINS + cg * RB_BINS) + q;
        int4 s = make_int4(0, 0, 0, 0);
#pragma unroll
        for (int j = 0; j < CHUNKS; ++j) {
            int4 p = part[j * (NBINS / 4)];
            s.x += p.x; s.y += p.y; s.z += p.z; s.w += p.w;
        }
        float* cf = (float*)cnt4;               // [bin*4 + image]
        cf[(4 * q + 0) * 4 + i] = (float)s.x;
        cf[(4 * q + 1) * 4 + i] = (float)s.y;
        cf[(4 * q + 2) * 4 + i] = (float)s.z;
        cf[(4 * q + 3) * 4 + i] = (float)s.w;
    }
    __syncthreads();

    // Phase 2: 32 broadcast LDS.128 + 4 independent FMA chains
    float a0 = 0.f, a1 = 0.f, a2 = 0.f, a3 = 0.f;
#pragma unroll
    for (int k = 0; k < KCH; ++k) {
        float4 cv = cnt4[4 * k + g];
        a0 = fmaf(cv.x, l[k], a0);
        a1 = fmaf(cv.y, l[k], a1);
        a2 = fmaf(cv.z, l[k], a2);
        a3 = fmaf(cv.w, l[k], a3);
    }
    red[g][0][c] = a0; red[g][1][c] = a1;
    red[g][2][c] = a2; red[g][3][c] = a3;
    __syncthreads();

    // combine 4 sub-chains, atomically accumulate into out
    {
        int i  = tid >> 6;                      // image within quad
        int ch = tid & 63;
        float s = red[0][i][ch] + red[1][i][ch] + red[2][i][ch] + red[3][i][ch];
        atomicAdd(&out[(ig * RB_IMGS + i) * OUTW + ch], s);
    }

    // marker check: one thread total; broadcast to all 32 rows
    if (cg == 0 && blockIdx.y == 0 && tid == 0) {
        uint32_t word = 0u;
#pragma unroll
        for (int j = 0; j < 32; ++j) {
            int bit = ((int)(alpha[j] * 255.0f)) & 1;
            word |= (uint32_t)bit << j;
        }
        float m = (__brev(word) == 0x41493234u) ? 1.0f : 0.0f;   // 'AI24'
        for (int b = 0; b < BATCH; ++b) out[b * OUTW + DIMC] = m;
    }
}

// ---------------------------------------------------------------------------
extern "C" void kernel_launch(void* const* d_in, const int* in_sizes, int n_in,
                              void* d_out, int out_size)
{
    const float* alpha  = (const float*)d_in[0];
    const float* conv_w = (const float*)d_in[1];
    const float* conv_b = (const float*)d_in[2];
    const float* bn_g   = (const float*)d_in[3];
    const float* bn_b   = (const float*)d_in[4];
    const float* bn_m   = (const float*)d_in[5];
    const float* bn_v   = (const float*)d_in[6];
    float* out = (float*)d_out;

    fused_kernel<<<HIST_BLOCKS + LUT_BLOCKS, 384>>>(
        alpha, conv_w, conv_b, bn_g, bn_b, bn_m, bn_v, out);
    reduce_kernel<<<dim3(BIN_GROUPS, IMG_GROUPS), 256>>>(alpha, out);
}

// round 6
// speedup vs baseline: 5.2851x; 1.0151x over previous
#include <cuda_runtime.h>
#include <cstdint>

#define DIMC 64
#define NBINS 4096
#define CHUNKS 6            // 64 rows per hist block (two 32-row passes)
#define IMG 384
#define WORDS 12            // 384 / 32
#define BATCH 32
#define OUTW 65
#define HIST_BLOCKS (BATCH * CHUNKS)    // 192
#define LUT_BLOCKS 64
#define RB_BINS 128         // reduce: bins per block
#define BIN_GROUPS (NBINS / RB_BINS)    // 32
#define KCH (RB_BINS / 4)   // 32 lut registers per thread

// Static device scratch (no allocations allowed).
// g_hist: per-image combined histograms. Zero at load; every launch the fused
// kernel adds into it and the reduce kernel restores it to zero -> replayable.
__device__ float g_lut[NBINS * DIMC];        // 1 MB
__device__ int   g_hist[BATCH * NBINS];      // 512 KB

// ---------------------------------------------------------------------------
// Fused kernel: blocks [0,192) histogram 64-row chunks of one image and
// RED.ADD the shared histogram into g_hist[image]; blocks [192,256) build
// the 12-bit pair LUT and zero d_out. One launch, one wave.
// The two 32-row passes are software-pipelined: pass-2 loads are issued
// before pass-1's shared atomics so DRAM latency hides behind atomic work.
// ---------------------------------------------------------------------------
__global__ __launch_bounds__(384) void fused_kernel(
    const float* __restrict__ alpha,
    const float* __restrict__ w, const float* __restrict__ bias,
    const float* __restrict__ gamma, const float* __restrict__ beta,
    const float* __restrict__ mean, const float* __restrict__ var,
    float* __restrict__ out)
{
    int tid = threadIdx.x;

    if (blockIdx.x >= HIST_BLOCKS) {
        // ---------------- LUT role ----------------
        int t = (blockIdx.x - HIST_BLOCKS) * 384 + tid;   // 0 .. 24575
        if (t < BATCH * OUTW) out[t] = 0.0f;              // zero-init output

        int c  = t & (DIMC - 1);
        int p0 = t >> 6;                                  // 0..383

        float A = gamma[c] * rsqrtf(var[c] + 1e-5f);
        float base = (bias[c] - mean[c]) * A + beta[c];
        float wk[9];
#pragma unroll
        for (int k = 0; k < 9; ++k) wk[k] = w[c * 9 + k];

        for (int p = p0; p < NBINS; p += 384) {
            float da = 0.f, db = 0.f;
#pragma unroll
            for (int ky = 0; ky < 3; ++ky)
#pragma unroll
                for (int kx = 0; kx < 3; ++kx) {
                    int bp = 4 * ky + kx;
                    if ((p >> bp) & 1)       da += wk[ky * 3 + kx];
                    if ((p >> (bp + 1)) & 1) db += wk[ky * 3 + kx];
                }
            float va = fmaxf(fmaf(A, da, base), 0.f);
            float vb = fmaxf(fmaf(A, db, base), 0.f);
            g_lut[p * DIMC + c] = (va + vb) * (1.0f / (384.0f * 384.0f));
        }
        return;
    }

    // ---------------- histogram role ----------------
    __shared__ uint32_t bits[2][34][WORDS + 2];   // double-buffered bit planes
    __shared__ int hist[NBINS];

    int b     = blockIdx.x / CHUNKS;
    int chunk = blockIdx.x % CHUNKS;
    int lane  = tid & 31;
    int warp  = tid >> 5;                      // 0..11 = word column

    for (int i = tid; i < NBINS; i += 384) hist[i] = 0;
    if (tid < 34) {
        bits[0][tid][0] = 0u; bits[0][tid][WORDS + 1] = 0u;
        bits[1][tid][0] = 0u; bits[1][tid][WORDS + 1] = 0u;
    }

    const float* img = alpha + (size_t)b * IMG * IMG;
    int r  = tid / WORDS;   // 0..31 local row  (384 = 32*12 exactly)
    int wd = tid % WORDS;
    int base0 = chunk * 64;
    int base1 = chunk * 64 + 32;

    // ---- pass 0: batched loads, ballots ----
    float v[34];
#pragma unroll
    for (int row = 0; row < 34; ++row) {
        int g = base0 - 1 + row;
        v[row] = (g >= 0 && g < IMG) ? img[g * IMG + warp * 32 + lane] : 0.0f;
    }
#pragma unroll
    for (int row = 0; row < 34; ++row) {
        uint32_t wb = __ballot_sync(0xffffffffu, ((int)(v[row] * 255.0f)) & 1);
        if (lane == 0) bits[0][row][warp + 1] = wb;
    }
    __syncthreads();

    // pick up pass-0 neighborhood words
    uint32_t p0 = bits[0][r][wd],     c0 = bits[0][r][wd + 1],     x0 = bits[0][r][wd + 2];
    uint32_t p1 = bits[0][r + 1][wd], c1 = bits[0][r + 1][wd + 1], x1 = bits[0][r + 1][wd + 2];
    uint32_t p2 = bits[0][r + 2][wd], c2 = bits[0][r + 2][wd + 1], x2 = bits[0][r + 2][wd + 2];

    // ---- issue pass-1 loads NOW (hide DRAM behind pass-0 atomics) ----
    float u[34];
#pragma unroll
    for (int row = 0; row < 34; ++row) {
        int g = base1 - 1 + row;
        u[row] = (g < IMG) ? img[g * IMG + warp * 32 + lane] : 0.0f;  // base1-1 >= 31 always
    }

    // ---- pass-0 shared atomics ----
    {
        uint32_t n0 = __funnelshift_r(p0, c0, 31) & 0xF;
        uint32_t n1 = __funnelshift_r(p1, c1, 31) & 0xF;
        uint32_t n2 = __funnelshift_r(p2, c2, 31) & 0xF;
        atomicAdd(&hist[n0 | (n1 << 4) | (n2 << 8)], 1);
    }
#pragma unroll
    for (int k = 1; k < 16; ++k) {
        uint32_t n0 = __funnelshift_r(c0, x0, 2 * k - 1) & 0xF;
        uint32_t n1 = __funnelshift_r(c1, x1, 2 * k - 1) & 0xF;
        uint32_t n2 = __funnelshift_r(c2, x2, 2 * k - 1) & 0xF;
        atomicAdd(&hist[n0 | (n1 << 4) | (n2 << 8)], 1);
    }

    // ---- pass-1 ballots into second buffer ----
#pragma unroll
    for (int row = 0; row < 34; ++row) {
        uint32_t wb = __ballot_sync(0xffffffffu, ((int)(u[row] * 255.0f)) & 1);
        if (lane == 0) bits[1][row][warp + 1] = wb;
    }
    __syncthreads();

    p0 = bits[1][r][wd];     c0 = bits[1][r][wd + 1];     x0 = bits[1][r][wd + 2];
    p1 = bits[1][r + 1][wd]; c1 = bits[1][r + 1][wd + 1]; x1 = bits[1][r + 1][wd + 2];
    p2 = bits[1][r + 2][wd]; c2 = bits[1][r + 2][wd + 1]; x2 = bits[1][r + 2][wd + 2];

    {
        uint32_t n0 = __funnelshift_r(p0, c0, 31) & 0xF;
        uint32_t n1 = __funnelshift_r(p1, c1, 31) & 0xF;
        uint32_t n2 = __funnelshift_r(p2, c2, 31) & 0xF;
        atomicAdd(&hist[n0 | (n1 << 4) | (n2 << 8)], 1);
    }
#pragma unroll
    for (int k = 1; k < 16; ++k) {
        uint32_t n0 = __funnelshift_r(c0, x0, 2 * k - 1) & 0xF;
        uint32_t n1 = __funnelshift_r(c1, x1, 2 * k - 1) & 0xF;
        uint32_t n2 = __funnelshift_r(c2, x2, 2 * k - 1) & 0xF;
        atomicAdd(&hist[n0 | (n1 << 4) | (n2 << 8)], 1);
    }
    __syncthreads();

    // flush: RED.ADD into the per-image combined histogram (no return value)
    int* dst = g_hist + b * NBINS;
    for (int i = tid; i < NBINS; i += 384) atomicAdd(&dst[i], hist[i]);
}

// ---------------------------------------------------------------------------
// Reduce: grid (32 bin-groups, 32 images) = 1024 blocks × 256 threads.
// Phase 1: one coalesced load of this block's 128-bin slice (then restore it
// to zero for the next graph replay). Phase 2: register-resident LUT chains.
// ---------------------------------------------------------------------------
__global__ __launch_bounds__(256) void reduce_kernel(
    const float* __restrict__ alpha, float* __restrict__ out)
{
    __shared__ float cnt[RB_BINS];
    __shared__ float red[4][DIMC];

    int tid = threadIdx.x;
    int cg  = blockIdx.x;                       // bins [cg*128, cg*128+128)
    int b   = blockIdx.y;                       // image

    int c = tid & 63;
    int g = tid >> 6;                           // 0..3 bin sub-chain

    // LUT into registers: one fully-batched, coalesced burst (MLP=32)
    const float* lut = g_lut + (size_t)cg * RB_BINS * DIMC + c;
    float l[KCH];
#pragma unroll
    for (int k = 0; k < KCH; ++k) l[k] = lut[(4 * k + g) * DIMC];

    // Phase 1: single coalesced slab read + restore-to-zero for replay
    if (tid < RB_BINS) {
        int* hp = g_hist + b * NBINS + cg * RB_BINS + tid;
        int s = *hp;
        *hp = 0;
        cnt[tid] = (float)s;
    }
    __syncthreads();

    // Phase 2: 32 broadcast LDS + FMA chain per thread
    float a = 0.f;
#pragma unroll
    for (int k = 0; k < KCH; ++k)
        a = fmaf(cnt[4 * k + g], l[k], a);
    red[g][c] = a;
    __syncthreads();

    if (tid < DIMC) {
        float s = red[0][tid] + red[1][tid] + red[2][tid] + red[3][tid];
        atomicAdd(&out[b * OUTW + tid], s);
    }

    // marker check: one thread total; broadcast to all 32 rows
    if (cg == 0 && b == 0 && tid == 0) {
        uint32_t word = 0u;
#pragma unroll
        for (int j = 0; j < 32; ++j) {
            int bit = ((int)(alpha[j] * 255.0f)) & 1;
            word |= (uint32_t)bit << j;
        }
        float m = (__brev(word) == 0x41493234u) ? 1.0f : 0.0f;   // 'AI24'
        for (int bb = 0; bb < BATCH; ++bb) out[bb * OUTW + DIMC] = m;
    }
}

// ---------------------------------------------------------------------------
extern "C" void kernel_launch(void* const* d_in, const int* in_sizes, int n_in,
                              void* d_out, int out_size)
{
    const float* alpha  = (const float*)d_in[0];
    const float* conv_w = (const float*)d_in[1];
    const float* conv_b = (const float*)d_in[2];
    const float* bn_g   = (const float*)d_in[3];
    const float* bn_b   = (const float*)d_in[4];
    const float* bn_m   = (const float*)d_in[5];
    const float* bn_v   = (const float*)d_in[6];
    float* out = (float*)d_out;

    fused_kernel<<<HIST_BLOCKS + LUT_BLOCKS, 384>>>(
        alpha, conv_w, conv_b, bn_g, bn_b, bn_m, bn_v, out);
    reduce_kernel<<<dim3(BIN_GROUPS, BATCH), 256>>>(alpha, out);
}